// round 5
// baseline (speedup 1.0000x reference)
#include <cuda_runtime.h>
#include <cuda_fp16.h>
#include <mma.h>
#include <cstdio>

using namespace nvcuda;

#define H 128
#define NLAY 3
#define LDS_PAD 136
#define STG_PAD 72
#define GEMM_BLOCKS 296
#define GEMM_SMEM ((H * LDS_PAD + 8 * 16 * STG_PAD) * (int)sizeof(float))  // 69632+36864=106496

static const int NMAXc  = 100000;
static const int EMAXc  = 600000;
static const int E2MAXc = 1500000;
static const int BMAXc  = 64;

// ---------------- scratch (device globals; allocation-free rule) -----------
__device__ float  d_hx[(size_t)(NMAXc + 64) * H];   // node features (fp32, pre-scaled, tf32-rounded)
__device__ float  d_ex[(size_t)(EMAXc + 64) * H];   // edge features
__device__ __half d_yh[(size_t)(NMAXc + 64) * H];   // node GEMM out (fp16)
__device__ __half d_ye[(size_t)(EMAXc + 64) * H];   // edge GEMM out (fp16)
__device__ int   d_cntG[2 * NMAXc];      // [0,N) out-deg, [N,2N) in-deg
__device__ int   d_cntL[2 * EMAXc];
__device__ float d_dinvG[2 * NMAXc];
__device__ float d_dinvL[2 * EMAXc];
__device__ int   d_offG[NMAXc];
__device__ int   d_offL[EMAXc];
__device__ int   d_curG[NMAXc];
__device__ int   d_curL[EMAXc];
__device__ int   d_eidxG[EMAXc];
__device__ int   d_eidxL[E2MAXc];
__device__ int   d_bsum[1024];
__device__ float d_red[2 * BMAXc * H + 2 * BMAXc];

// ---------------- helpers --------------------------------------------------
__device__ __forceinline__ void red_add_v4(float* p, float4 v) {
    asm volatile("red.global.add.v4.f32 [%0], {%1,%2,%3,%4};"
                 :: "l"(p), "f"(v.x), "f"(v.y), "f"(v.z), "f"(v.w) : "memory");
}
__device__ __forceinline__ float to_tf32(float x) {
    float r; asm("cvt.rna.tf32.f32 %0, %1;" : "=f"(r) : "f"(x)); return r;
}

// ---------------- small utility kernels ------------------------------------
__global__ void k_zero_f4(float4* __restrict__ p, long long n4) {
    long long i = (long long)blockIdx.x * blockDim.x + threadIdx.x;
    long long st = (long long)gridDim.x * blockDim.x;
    float4 z = make_float4(0.f, 0.f, 0.f, 0.f);
    for (; i < n4; i += st) p[i] = z;
}

__global__ void k_count(const int* __restrict__ s, const int* __restrict__ t,
                        int* __restrict__ co, int* __restrict__ ci, int m) {
    int i = blockIdx.x * blockDim.x + threadIdx.x;
    int st = gridDim.x * blockDim.x;
    for (; i < m; i += st) {
        atomicAdd(&co[s[i]], 1);
        atomicAdd(&ci[t[i]], 1);
    }
}

__global__ void k_dinv(const int* __restrict__ c, float* __restrict__ dv, int n) {
    int i = blockIdx.x * blockDim.x + threadIdx.x;
    int st = gridDim.x * blockDim.x;
    for (; i < n; i += st) dv[i] = rsqrtf(fmaxf((float)c[i], 1.f));
}

__global__ void k_copy_i(const int* __restrict__ a, int* __restrict__ b, int n) {
    int i = blockIdx.x * blockDim.x + threadIdx.x;
    int st = gridDim.x * blockDim.x;
    for (; i < n; i += st) b[i] = a[i];
}

__global__ void k_segcnt(const int* __restrict__ seg, float* __restrict__ cnt, int n) {
    int i = blockIdx.x * blockDim.x + threadIdx.x;
    int st = gridDim.x * blockDim.x;
    for (; i < n; i += st) atomicAdd(&cnt[seg[i]], 1.f);
}

// ---------------- scan (exclusive, 3 kernels) ------------------------------
#define SCAN_ELEMS 4096
__global__ void k_scan1(const int* __restrict__ in, int* __restrict__ out,
                        int* __restrict__ bsum, int n) {
    __shared__ int sh[32];
    int t = threadIdx.x;
    int base = blockIdx.x * SCAN_ELEMS + t * 4;
    int4 v = make_int4(0, 0, 0, 0);
    if (base + 3 < n) v = *(const int4*)(in + base);
    else {
        if (base     < n) v.x = in[base];
        if (base + 1 < n) v.y = in[base + 1];
        if (base + 2 < n) v.z = in[base + 2];
        if (base + 3 < n) v.w = in[base + 3];
    }
    int s = v.x + v.y + v.z + v.w;
    int lane = t & 31, wid = t >> 5;
    int p = s;
    #pragma unroll
    for (int o = 1; o < 32; o <<= 1) {
        int q = __shfl_up_sync(0xffffffffu, p, o);
        if (lane >= o) p += q;
    }
    if (lane == 31) sh[wid] = p;
    __syncthreads();
    if (wid == 0) {
        int q = sh[lane];
        #pragma unroll
        for (int o = 1; o < 32; o <<= 1) {
            int r = __shfl_up_sync(0xffffffffu, q, o);
            if (lane >= o) q += r;
        }
        sh[lane] = q;
    }
    __syncthreads();
    int excl = p - s + (wid ? sh[wid - 1] : 0);
    int4 o4;
    o4.x = excl; o4.y = excl + v.x; o4.z = o4.y + v.y; o4.w = o4.z + v.z;
    if (base + 3 < n) *(int4*)(out + base) = o4;
    else {
        if (base     < n) out[base]     = o4.x;
        if (base + 1 < n) out[base + 1] = o4.y;
        if (base + 2 < n) out[base + 2] = o4.z;
        if (base + 3 < n) out[base + 3] = o4.w;
    }
    if (t == 1023) bsum[blockIdx.x] = excl + s;
}

__global__ void k_scan2(int* __restrict__ bsum, int nb) {
    __shared__ int sh[32];
    int t = threadIdx.x;
    int v = (t < nb) ? bsum[t] : 0;
    int lane = t & 31, wid = t >> 5;
    int p = v;
    #pragma unroll
    for (int o = 1; o < 32; o <<= 1) {
        int q = __shfl_up_sync(0xffffffffu, p, o);
        if (lane >= o) p += q;
    }
    if (lane == 31) sh[wid] = p;
    __syncthreads();
    if (wid == 0) {
        int q = sh[lane];
        #pragma unroll
        for (int o = 1; o < 32; o <<= 1) {
            int r = __shfl_up_sync(0xffffffffu, q, o);
            if (lane >= o) q += r;
        }
        sh[lane] = q;
    }
    __syncthreads();
    int excl = p - v + (wid ? sh[wid - 1] : 0);
    if (t < nb) bsum[t] = excl;
}

__global__ void k_scan3(int* __restrict__ out, const int* __restrict__ bsum, int n) {
    int add = bsum[blockIdx.x];
    int base = blockIdx.x * SCAN_ELEMS + threadIdx.x * 4;
    #pragma unroll
    for (int j = 0; j < 4; j++)
        if (base + j < n) out[base + j] += add;
}

__global__ void k_fill(const int* __restrict__ s, const int* __restrict__ t,
                       int* __restrict__ cur, int* __restrict__ eidx, int m) {
    int i = blockIdx.x * blockDim.x + threadIdx.x;
    int st = gridDim.x * blockDim.x;
    for (; i < m; i += st) {
        int v = t[i];
        int pos = atomicAdd(&cur[v], 1);
        eidx[pos] = s[i];
    }
}

// ---------------- feature init (pre-scaled by deg_out^-1/2, tf32-rounded) --
__global__ void k_init_h(const int* __restrict__ z, const float* __restrict__ emb,
                         const float* __restrict__ dout, float* __restrict__ h, int n) {
    int gid = blockIdx.x * blockDim.x + threadIdx.x;
    int node = gid >> 5, lane = gid & 31;
    if (node >= n) return;
    int zz = __ldg(&z[node]);
    float sc = __ldg(&dout[node]);
    float4 v = *(const float4*)(emb + (size_t)zz * H + lane * 4);
    v.x = to_tf32(v.x * sc); v.y = to_tf32(v.y * sc);
    v.z = to_tf32(v.z * sc); v.w = to_tf32(v.w * sc);
    *(float4*)(h + (size_t)node * H + lane * 4) = v;
}

__global__ void k_init_e(const float* __restrict__ d, const float* __restrict__ w,
                         const float* __restrict__ b, const float* __restrict__ dout,
                         float* __restrict__ e, int m) {
    int gid = blockIdx.x * blockDim.x + threadIdx.x;
    int i = gid >> 5, lane = gid & 31;
    if (i >= m) return;
    float dv = __ldg(&d[i]);
    float sc = __ldg(&dout[i]);
    float4 wv = *(const float4*)(w + lane * 4);
    float4 bv = *(const float4*)(b + lane * 4);
    float4 o;
    o.x = to_tf32((dv * wv.x + bv.x) * sc);
    o.y = to_tf32((dv * wv.y + bv.y) * sc);
    o.z = to_tf32((dv * wv.z + bv.z) * sc);
    o.w = to_tf32((dv * wv.w + bv.w) * sc);
    *(float4*)(e + (size_t)i * H + lane * 4) = o;
}

// ---------------- TF32 GEMM: y(fp16) = x @ W; A direct from global ---------
__global__ __launch_bounds__(256) void k_gemm(const float* __restrict__ x,
                                              const float* __restrict__ W,
                                              __half* __restrict__ y, int n) {
    extern __shared__ float sh[];
    float* Ws = sh;                  // H x LDS_PAD (tf32-rounded)
    int tid = threadIdx.x;

    #pragma unroll
    for (int q = 0; q < 16; q++) {
        int i = tid + q * 256;           // 4096 float4
        int r = i >> 5; int c4 = (i & 31) * 4;
        float4 v = *(const float4*)(W + r * H + c4);
        v.x = to_tf32(v.x); v.y = to_tf32(v.y);
        v.z = to_tf32(v.z); v.w = to_tf32(v.w);
        *(float4*)(Ws + r * LDS_PAD + c4) = v;
    }
    __syncthreads();

    int warp = tid >> 5, lane = tid & 31;
    int rt = warp & 3;               // 16-row slice within 64-row tile
    int ch = warp >> 2;              // 64-col half
    float* stg = sh + H * LDS_PAD + warp * (16 * STG_PAD);

    int ntiles = (n + 63) >> 6;
    for (int tile = blockIdx.x; tile < ntiles; tile += gridDim.x) {
        int row0 = tile * 64 + rt * 16;

        wmma::fragment<wmma::accumulator, 16, 16, 8, float> fc[4];
        #pragma unroll
        for (int t = 0; t < 4; t++) wmma::fill_fragment(fc[t], 0.f);

        #pragma unroll
        for (int k = 0; k < H; k += 8) {
            wmma::fragment<wmma::matrix_a, 16, 16, 8, wmma::precision::tf32, wmma::row_major> fa;
            wmma::load_matrix_sync(fa, x + (size_t)row0 * H + k, H);
            #pragma unroll
            for (int t = 0; t < 4; t++) {
                wmma::fragment<wmma::matrix_b, 16, 16, 8, wmma::precision::tf32, wmma::row_major> fb;
                wmma::load_matrix_sync(fb, Ws + k * LDS_PAD + ch * 64 + t * 16, LDS_PAD);
                wmma::mma_sync(fc[t], fa, fb, fc[t]);
            }
        }
        // epilogue: fp32 -> fp16 via per-warp private smem patch
        #pragma unroll
        for (int t = 0; t < 4; t++)
            wmma::store_matrix_sync(stg + t * 16, fc[t], STG_PAD, wmma::mem_row_major);
        __syncwarp();
        #pragma unroll
        for (int i = 0; i < 4; i++) {
            int idx = lane + i * 32;        // 0..127
            int r = idx >> 3;               // 0..15
            int c8 = (idx & 7) * 8;         // 0..56
            float4 a = *(float4*)(stg + r * STG_PAD + c8);
            float4 b = *(float4*)(stg + r * STG_PAD + c8 + 4);
            __half2 h0 = __floats2half2_rn(a.x, a.y);
            __half2 h1 = __floats2half2_rn(a.z, a.w);
            __half2 h2 = __floats2half2_rn(b.x, b.y);
            __half2 h3 = __floats2half2_rn(b.z, b.w);
            uint4 o;
            o.x = *(unsigned*)&h0; o.y = *(unsigned*)&h1;
            o.z = *(unsigned*)&h2; o.w = *(unsigned*)&h3;
            *(uint4*)(y + (size_t)(row0 + r) * H + ch * 64 + c8) = o;
        }
        __syncwarp();
    }
}

// ---------------- CSR gather aggregation + fused epilogue ------------------
// o = relu(din[v]*sum y[eidx] + b); LAST: red into gsum, else write to_tf32(o*dout[v])
template<int LAST>
__global__ void k_agg(const __half* __restrict__ y, const int* __restrict__ eidx,
                      const int* __restrict__ off, const int* __restrict__ cnt,
                      const float* __restrict__ din, const float* __restrict__ dout,
                      const float* __restrict__ bias,
                      float* __restrict__ xo, const int* __restrict__ seg,
                      float* __restrict__ gsum, int n) {
    int gid = blockIdx.x * blockDim.x + threadIdx.x;
    int v = gid >> 5, lane = gid & 31;
    if (v >= n) return;
    int start = __ldg(&off[v]);
    int deg = __ldg(&cnt[v]);
    float4 acc = make_float4(0.f, 0.f, 0.f, 0.f);
    int j = 0;
    for (; j + 2 <= deg; j += 2) {
        int u0 = __ldg(&eidx[start + j]);
        int u1 = __ldg(&eidx[start + j + 1]);
        uint2 q0 = __ldg((const uint2*)(y + (size_t)u0 * H) + lane);
        uint2 q1 = __ldg((const uint2*)(y + (size_t)u1 * H) + lane);
        float2 a0 = __half22float2(*(__half2*)&q0.x);
        float2 a1 = __half22float2(*(__half2*)&q0.y);
        float2 b0 = __half22float2(*(__half2*)&q1.x);
        float2 b1 = __half22float2(*(__half2*)&q1.y);
        acc.x += a0.x + b0.x; acc.y += a0.y + b0.y;
        acc.z += a1.x + b1.x; acc.w += a1.y + b1.y;
    }
    if (j < deg) {
        int u = __ldg(&eidx[start + j]);
        uint2 q = __ldg((const uint2*)(y + (size_t)u * H) + lane);
        float2 a0 = __half22float2(*(__half2*)&q.x);
        float2 a1 = __half22float2(*(__half2*)&q.y);
        acc.x += a0.x; acc.y += a0.y; acc.z += a1.x; acc.w += a1.y;
    }
    float s = __ldg(&din[v]);
    float4 bb = *(const float4*)(bias + lane * 4);
    float4 o;
    o.x = fmaxf(fmaf(s, acc.x, bb.x), 0.f);
    o.y = fmaxf(fmaf(s, acc.y, bb.y), 0.f);
    o.z = fmaxf(fmaf(s, acc.z, bb.z), 0.f);
    o.w = fmaxf(fmaf(s, acc.w, bb.w), 0.f);
    if (LAST) {
        int g = __ldg(&seg[v]);
        red_add_v4(gsum + (size_t)g * H + lane * 4, o);
    } else {
        float sc = __ldg(&dout[v]);
        o.x = to_tf32(o.x * sc); o.y = to_tf32(o.y * sc);
        o.z = to_tf32(o.z * sc); o.w = to_tf32(o.w * sc);
        *(float4*)(xo + (size_t)v * H + lane * 4) = o;
    }
}

// ---------------- readout MLP ----------------------------------------------
__global__ void k_mlp(const float* __restrict__ gsum, const float* __restrict__ esum,
                      const float* __restrict__ gcnt, const float* __restrict__ ecnt,
                      const float* __restrict__ r1w, const float* __restrict__ r1b,
                      const float* __restrict__ r2w, const float* __restrict__ r2b,
                      float* __restrict__ out) {
    __shared__ float x[2 * H];
    __shared__ float red[4];
    int b = blockIdx.x;
    int j = threadIdx.x;
    float ig = 1.f / fmaxf(gcnt[b], 1.f);
    float ie = 1.f / fmaxf(ecnt[b], 1.f);
    x[j]     = gsum[b * H + j] * ig;
    x[H + j] = esum[b * H + j] * ie;
    __syncthreads();
    float acc = __ldg(&r1b[j]);
    #pragma unroll 8
    for (int i = 0; i < 2 * H; i++) acc += x[i] * __ldg(&r1w[i * H + j]);
    float sig = 1.f / (1.f + expf(-acc));
    float val = acc * sig * __ldg(&r2w[j]);
    #pragma unroll
    for (int o = 16; o > 0; o >>= 1) val += __shfl_xor_sync(0xffffffffu, val, o);
    if ((j & 31) == 0) red[j >> 5] = val;
    __syncthreads();
    if (j == 0) out[b] = red[0] + red[1] + red[2] + red[3] + __ldg(&r2b[0]);
}

// ---------------- host -----------------------------------------------------
static inline int zgrid(long long n4) {
    long long b = (n4 + 255) / 256;
    return (int)(b < 8192 ? b : 8192);
}

extern "C" void kernel_launch(void* const* d_in, const int* in_sizes, int n_in,
                              void* d_out, int out_size) {
    const int*   z    = (const int*)d_in[0];
    const float* dd   = (const float*)d_in[1];
    const int*   src  = (const int*)d_in[2];
    const int*   dst  = (const int*)d_in[3];
    const int*   lsrc = (const int*)d_in[4];
    const int*   ldst = (const int*)d_in[5];
    const int*   ng   = (const int*)d_in[6];
    const int*   eg   = (const int*)d_in[7];
    const float* emb  = (const float*)d_in[8];
    const float* epw  = (const float*)d_in[9];
    const float* epb  = (const float*)d_in[10];
    const float* gW   = (const float*)d_in[11];
    const float* gb   = (const float*)d_in[12];
    const float* lgW  = (const float*)d_in[13];
    const float* lgb  = (const float*)d_in[14];
    const float* r1w  = (const float*)d_in[15];
    const float* r1b  = (const float*)d_in[16];
    const float* r2w  = (const float*)d_in[17];
    const float* r2b  = (const float*)d_in[18];

    int N  = in_sizes[0];
    int E  = in_sizes[2];
    int E2 = in_sizes[4];
    int B  = out_size;
    float* out = (float*)d_out;

    float *hx, *ex, *dinvG, *dinvL, *red;
    __half *yh, *ye;
    int *cntG, *cntL, *offG, *offL, *curG, *curL, *eidxG, *eidxL, *bsum;
    cudaGetSymbolAddress((void**)&hx, d_hx);
    cudaGetSymbolAddress((void**)&ex, d_ex);
    cudaGetSymbolAddress((void**)&yh, d_yh);
    cudaGetSymbolAddress((void**)&ye, d_ye);
    cudaGetSymbolAddress((void**)&cntG, d_cntG);
    cudaGetSymbolAddress((void**)&cntL, d_cntL);
    cudaGetSymbolAddress((void**)&dinvG, d_dinvG);
    cudaGetSymbolAddress((void**)&dinvL, d_dinvL);
    cudaGetSymbolAddress((void**)&offG, d_offG);
    cudaGetSymbolAddress((void**)&offL, d_offL);
    cudaGetSymbolAddress((void**)&curG, d_curG);
    cudaGetSymbolAddress((void**)&curL, d_curL);
    cudaGetSymbolAddress((void**)&eidxG, d_eidxG);
    cudaGetSymbolAddress((void**)&eidxL, d_eidxL);
    cudaGetSymbolAddress((void**)&bsum, d_bsum);
    cudaGetSymbolAddress((void**)&red, d_red);

    float* gsum = red;
    float* esum = red + (size_t)B * H;
    float* gcnt = red + (size_t)2 * B * H;
    float* ecnt = gcnt + B;

    cudaFuncSetAttribute(k_gemm, cudaFuncAttributeMaxDynamicSharedMemorySize, GEMM_SMEM);

    // ---- line-graph front matter (ordered so ncu skip-5 captures k_gemm) ----
    k_zero_f4<<<zgrid((long long)2 * E / 4), 256>>>((float4*)cntL, (long long)2 * E / 4);   // 1
    k_count<<<2048, 256>>>(lsrc, ldst, cntL, cntL + E, E2);                                  // 2
    k_dinv<<<2048, 256>>>(cntL, dinvL, 2 * E);                                               // 3
    k_init_e<<<((long long)E * 32 + 255) / 256, 256>>>(dd, epw, epb, dinvL, ex, E);          // 4
    k_gemm<<<GEMM_BLOCKS, 256, GEMM_SMEM>>>(ex, lgW, ye, E);                                 // 5 <- profiled
    {
        long long nred4 = ((long long)2 * B * H + 2 * B) / 4;
        k_zero_f4<<<zgrid(nred4), 256>>>((float4*)red, nred4);                               // 6
    }

    // ---- node-graph front matter ----
    k_zero_f4<<<zgrid((long long)2 * N / 4), 256>>>((float4*)cntG, (long long)2 * N / 4);
    k_count<<<2048, 256>>>(src, dst, cntG, cntG + N, E);
    k_dinv<<<2048, 256>>>(cntG, dinvG, 2 * N);
    k_init_h<<<((long long)N * 32 + 255) / 256, 256>>>(z, emb, dinvG, hx, N);

    // ---- CSR by destination (line graph) ----
    int nbL = (E + SCAN_ELEMS - 1) / SCAN_ELEMS;
    k_scan1<<<nbL, 1024>>>(cntL + E, offL, bsum, E);
    k_scan2<<<1, 1024>>>(bsum, nbL);
    k_scan3<<<nbL, 1024>>>(offL, bsum, E);
    k_copy_i<<<2048, 256>>>(offL, curL, E);
    k_fill<<<2048, 256>>>(lsrc, ldst, curL, eidxL, E2);

    // ---- line-graph layers ----
    long long aggE = ((long long)E * 32 + 255) / 256;
    k_agg<0><<<aggE, 256>>>(ye, eidxL, offL, cntL + E, dinvL + E, dinvL,
                            lgb, ex, eg, esum, E);
    for (int l = 1; l < NLAY; l++) {
        k_gemm<<<GEMM_BLOCKS, 256, GEMM_SMEM>>>(ex, lgW + (size_t)l * H * H, ye, E);
        if (l < NLAY - 1)
            k_agg<0><<<aggE, 256>>>(ye, eidxL, offL, cntL + E, dinvL + E, dinvL,
                                    lgb + (size_t)l * H, ex, eg, esum, E);
        else
            k_agg<1><<<aggE, 256>>>(ye, eidxL, offL, cntL + E, dinvL + E, dinvL,
                                    lgb + (size_t)l * H, ex, eg, esum, E);
    }

    // ---- CSR by destination (node graph) ----
    int nbG = (N + SCAN_ELEMS - 1) / SCAN_ELEMS;
    k_scan1<<<nbG, 1024>>>(cntG + N, offG, bsum, N);
    k_scan2<<<1, 1024>>>(bsum, nbG);
    k_scan3<<<nbG, 1024>>>(offG, bsum, N);
    k_copy_i<<<512, 256>>>(offG, curG, N);
    k_fill<<<2048, 256>>>(src, dst, curG, eidxG, E);

    // ---- node-graph layers ----
    long long aggN = ((long long)N * 32 + 255) / 256;
    for (int l = 0; l < NLAY; l++) {
        k_gemm<<<GEMM_BLOCKS, 256, GEMM_SMEM>>>(hx, gW + (size_t)l * H * H, yh, N);
        if (l < NLAY - 1)
            k_agg<0><<<aggN, 256>>>(yh, eidxG, offG, cntG + N, dinvG + N, dinvG,
                                    gb + (size_t)l * H, hx, ng, gsum, N);
        else
            k_agg<1><<<aggN, 256>>>(yh, eidxG, offG, cntG + N, dinvG + N, dinvG,
                                    gb + (size_t)l * H, hx, ng, gsum, N);
    }

    // ---- per-graph counts + readout ----
    k_segcnt<<<512, 256>>>(ng, gcnt, N);
    k_segcnt<<<2048, 256>>>(eg, ecnt, E);
    k_mlp<<<B, 128>>>(gsum, esum, gcnt, ecnt, r1w, r1b, r2w, r2b, out);
}

// round 6
// speedup vs baseline: 1.2862x; 1.2862x over previous
#include <cuda_runtime.h>
#include <cuda_fp16.h>
#include <mma.h>
#include <cstdio>

using namespace nvcuda;

#define H 128
#define NLAY 3
#define SPAD 136                      // half-elem stride for smem tiles (272 B)
#define GEMM_BLOCKS 592
#define GEMM_SMEM ((H * SPAD + 64 * SPAD) * (int)sizeof(__half))   // 52224 B

static const int NMAXc  = 100000;
static const int EMAXc  = 600000;
static const int E2MAXc = 1500000;
static const int BMAXc  = 64;

// ---------------- scratch (device globals; allocation-free rule) -----------
__device__ __half d_hx[(size_t)(NMAXc + 64) * H];
__device__ __half d_ex[(size_t)(EMAXc + 64) * H];
__device__ __half d_yh[(size_t)(NMAXc + 64) * H];
__device__ __half d_ye[(size_t)(EMAXc + 64) * H];
__device__ int   d_cntG[2 * NMAXc];      // [0,N) out-deg, [N,2N) in-deg
__device__ int   d_cntL[2 * EMAXc];
__device__ int   d_offG[NMAXc];
__device__ int   d_offL[EMAXc];
__device__ int   d_curG[NMAXc];
__device__ int   d_curL[EMAXc];
__device__ int   d_eidxG[EMAXc];
__device__ int   d_eidxL[E2MAXc];
__device__ int   d_bsum[1024];
__device__ float d_red[2 * BMAXc * H + 2 * BMAXc];

// ---------------- helpers --------------------------------------------------
__device__ __forceinline__ void red_add_v4(float* p, float4 v) {
    asm volatile("red.global.add.v4.f32 [%0], {%1,%2,%3,%4};"
                 :: "l"(p), "f"(v.x), "f"(v.y), "f"(v.z), "f"(v.w) : "memory");
}
__device__ __forceinline__ float rsq_deg(int c) {
    return rsqrtf(fmaxf((float)c, 1.f));
}

// ---------------- small utility kernels ------------------------------------
__global__ void k_zero_f4(float4* __restrict__ p, long long n4) {
    long long i = (long long)blockIdx.x * blockDim.x + threadIdx.x;
    long long st = (long long)gridDim.x * blockDim.x;
    float4 z = make_float4(0.f, 0.f, 0.f, 0.f);
    for (; i < n4; i += st) p[i] = z;
}

__global__ void k_count(const int* __restrict__ s, const int* __restrict__ t,
                        int* __restrict__ co, int* __restrict__ ci, int m) {
    int i = blockIdx.x * blockDim.x + threadIdx.x;
    int st = gridDim.x * blockDim.x;
    for (; i < m; i += st) {
        atomicAdd(&co[s[i]], 1);
        atomicAdd(&ci[t[i]], 1);
    }
}

__global__ void k_copy_i(const int* __restrict__ a, int* __restrict__ b, int n) {
    int i = blockIdx.x * blockDim.x + threadIdx.x;
    int st = gridDim.x * blockDim.x;
    for (; i < n; i += st) b[i] = a[i];
}

__global__ void k_segcnt(const int* __restrict__ seg, float* __restrict__ cnt, int n) {
    int i = blockIdx.x * blockDim.x + threadIdx.x;
    int st = gridDim.x * blockDim.x;
    for (; i < n; i += st) atomicAdd(&cnt[seg[i]], 1.f);
}

// ---------------- scan (exclusive, 3 kernels) ------------------------------
#define SCAN_ELEMS 4096
__global__ void k_scan1(const int* __restrict__ in, int* __restrict__ out,
                        int* __restrict__ bsum, int n) {
    __shared__ int sh[32];
    int t = threadIdx.x;
    int base = blockIdx.x * SCAN_ELEMS + t * 4;
    int4 v = make_int4(0, 0, 0, 0);
    if (base + 3 < n) v = *(const int4*)(in + base);
    else {
        if (base     < n) v.x = in[base];
        if (base + 1 < n) v.y = in[base + 1];
        if (base + 2 < n) v.z = in[base + 2];
        if (base + 3 < n) v.w = in[base + 3];
    }
    int s = v.x + v.y + v.z + v.w;
    int lane = t & 31, wid = t >> 5;
    int p = s;
    #pragma unroll
    for (int o = 1; o < 32; o <<= 1) {
        int q = __shfl_up_sync(0xffffffffu, p, o);
        if (lane >= o) p += q;
    }
    if (lane == 31) sh[wid] = p;
    __syncthreads();
    if (wid == 0) {
        int q = sh[lane];
        #pragma unroll
        for (int o = 1; o < 32; o <<= 1) {
            int r = __shfl_up_sync(0xffffffffu, q, o);
            if (lane >= o) q += r;
        }
        sh[lane] = q;
    }
    __syncthreads();
    int excl = p - s + (wid ? sh[wid - 1] : 0);
    int4 o4;
    o4.x = excl; o4.y = excl + v.x; o4.z = o4.y + v.y; o4.w = o4.z + v.z;
    if (base + 3 < n) *(int4*)(out + base) = o4;
    else {
        if (base     < n) out[base]     = o4.x;
        if (base + 1 < n) out[base + 1] = o4.y;
        if (base + 2 < n) out[base + 2] = o4.z;
        if (base + 3 < n) out[base + 3] = o4.w;
    }
    if (t == 1023) bsum[blockIdx.x] = excl + s;
}

__global__ void k_scan2(int* __restrict__ bsum, int nb) {
    __shared__ int sh[32];
    int t = threadIdx.x;
    int v = (t < nb) ? bsum[t] : 0;
    int lane = t & 31, wid = t >> 5;
    int p = v;
    #pragma unroll
    for (int o = 1; o < 32; o <<= 1) {
        int q = __shfl_up_sync(0xffffffffu, p, o);
        if (lane >= o) p += q;
    }
    if (lane == 31) sh[wid] = p;
    __syncthreads();
    if (wid == 0) {
        int q = sh[lane];
        #pragma unroll
        for (int o = 1; o < 32; o <<= 1) {
            int r = __shfl_up_sync(0xffffffffu, q, o);
            if (lane >= o) q += r;
        }
        sh[lane] = q;
    }
    __syncthreads();
    int excl = p - v + (wid ? sh[wid - 1] : 0);
    if (t < nb) bsum[t] = excl;
}

__global__ void k_scan3(int* __restrict__ out, const int* __restrict__ bsum, int n) {
    int add = bsum[blockIdx.x];
    int base = blockIdx.x * SCAN_ELEMS + threadIdx.x * 4;
    #pragma unroll
    for (int j = 0; j < 4; j++)
        if (base + j < n) out[base + j] += add;
}

__global__ void k_fill(const int* __restrict__ s, const int* __restrict__ t,
                       int* __restrict__ cur, int* __restrict__ eidx, int m) {
    int i = blockIdx.x * blockDim.x + threadIdx.x;
    int st = gridDim.x * blockDim.x;
    for (; i < m; i += st) {
        int v = t[i];
        int pos = atomicAdd(&cur[v], 1);
        eidx[pos] = s[i];
    }
}

// ---------------- feature init (pre-scaled by deg_out^-1/2, fp16) ----------
__global__ void k_init_h(const int* __restrict__ z, const float* __restrict__ emb,
                         const int* __restrict__ co, __half* __restrict__ h, int n) {
    int gid = blockIdx.x * blockDim.x + threadIdx.x;
    int node = gid >> 5, lane = gid & 31;
    if (node >= n) return;
    int zz = __ldg(&z[node]);
    float sc = rsq_deg(__ldg(&co[node]));
    float4 v = *(const float4*)(emb + (size_t)zz * H + lane * 4);
    __half2 h0 = __floats2half2_rn(v.x * sc, v.y * sc);
    __half2 h1 = __floats2half2_rn(v.z * sc, v.w * sc);
    uint2 o; o.x = *(unsigned*)&h0; o.y = *(unsigned*)&h1;
    *(uint2*)(h + (size_t)node * H + lane * 4) = o;
}

__global__ void k_init_e(const float* __restrict__ d, const float* __restrict__ w,
                         const float* __restrict__ b, const int* __restrict__ co,
                         __half* __restrict__ e, int m) {
    int gid = blockIdx.x * blockDim.x + threadIdx.x;
    int i = gid >> 5, lane = gid & 31;
    if (i >= m) return;
    float dv = __ldg(&d[i]);
    float sc = rsq_deg(__ldg(&co[i]));
    float4 wv = *(const float4*)(w + lane * 4);
    float4 bv = *(const float4*)(b + lane * 4);
    __half2 h0 = __floats2half2_rn((dv * wv.x + bv.x) * sc, (dv * wv.y + bv.y) * sc);
    __half2 h1 = __floats2half2_rn((dv * wv.z + bv.z) * sc, (dv * wv.w + bv.w) * sc);
    uint2 o; o.x = *(unsigned*)&h0; o.y = *(unsigned*)&h1;
    *(uint2*)(e + (size_t)i * H + lane * 4) = o;
}

// ---------------- half GEMM: y = x @ W (fp32 accum, fp16 out) --------------
__global__ __launch_bounds__(256) void k_gemm(const __half* __restrict__ x,
                                              const float* __restrict__ W,
                                              __half* __restrict__ y, int n) {
    extern __shared__ __half sh[];
    __half* Ws = sh;                // H x SPAD
    __half* As = sh + H * SPAD;     // 64 x SPAD
    int tid = threadIdx.x;

    // stage W (fp32 -> fp16)
    #pragma unroll
    for (int q = 0; q < 16; q++) {
        int i = tid + q * 256;           // 4096 float4 reads
        int r = i >> 5; int c4 = (i & 31) * 4;
        float4 v = *(const float4*)(W + r * H + c4);
        __half2 h0 = __floats2half2_rn(v.x, v.y);
        __half2 h1 = __floats2half2_rn(v.z, v.w);
        uint2 o; o.x = *(unsigned*)&h0; o.y = *(unsigned*)&h1;
        *(uint2*)(Ws + r * SPAD + c4) = o;
    }

    int warp = tid >> 5;
    int rt = warp & 3;               // 16-row slice of 64-row tile
    int ch = warp >> 2;              // 64-col half

    int ntiles = (n + 63) >> 6;
    for (int tile = blockIdx.x; tile < ntiles; tile += gridDim.x) {
        int row0 = tile * 64;
        __syncthreads();
        // stage 64 rows of x (fp16, 16 KB), uint4 per thread x4
        #pragma unroll
        for (int q = 0; q < 4; q++) {
            int i = tid + q * 256;       // 1024 uint4
            int r = i >> 4; int c16 = (i & 15) * 8;
            uint4 v = *(const uint4*)(x + (size_t)(row0 + r) * H + c16);
            *(uint4*)(As + r * SPAD + c16) = v;
        }
        __syncthreads();

        wmma::fragment<wmma::accumulator, 16, 16, 16, float> fc[4];
        #pragma unroll
        for (int t = 0; t < 4; t++) wmma::fill_fragment(fc[t], 0.f);

        #pragma unroll
        for (int k = 0; k < H; k += 16) {
            wmma::fragment<wmma::matrix_a, 16, 16, 16, __half, wmma::row_major> fa;
            wmma::load_matrix_sync(fa, As + rt * 16 * SPAD + k, SPAD);
            #pragma unroll
            for (int t = 0; t < 4; t++) {
                wmma::fragment<wmma::matrix_b, 16, 16, 16, __half, wmma::row_major> fb;
                wmma::load_matrix_sync(fb, Ws + k * SPAD + ch * 64 + t * 16, SPAD);
                wmma::mma_sync(fc[t], fa, fb, fc[t]);
            }
        }
        #pragma unroll
        for (int t = 0; t < 4; t++) {
            wmma::fragment<wmma::accumulator, 16, 16, 16, __half> hc;
            #pragma unroll
            for (int i = 0; i < hc.num_elements; i++)
                hc.x[i] = __float2half(fc[t].x[i]);
            wmma::store_matrix_sync(y + (size_t)(row0 + rt * 16) * H + ch * 64 + t * 16,
                                    hc, H, wmma::mem_row_major);
        }
    }
}

// ---------------- CSR gather aggregation + fused epilogue ------------------
// o = relu(din*sum y[eidx] + b); LAST: red into gsum, else write fp16(o*dout)
template<int LAST>
__global__ void k_agg(const __half* __restrict__ y, const int* __restrict__ eidx,
                      const int* __restrict__ off, const int* __restrict__ ci,
                      const int* __restrict__ co, const float* __restrict__ bias,
                      __half* __restrict__ xo, const int* __restrict__ seg,
                      float* __restrict__ gsum, int n) {
    int gid = blockIdx.x * blockDim.x + threadIdx.x;
    int v = gid >> 5, lane = gid & 31;
    if (v >= n) return;
    int start = __ldg(&off[v]);
    int deg = __ldg(&ci[v]);
    float4 acc = make_float4(0.f, 0.f, 0.f, 0.f);
    int j = 0;
    for (; j + 2 <= deg; j += 2) {
        int u0 = __ldg(&eidx[start + j]);
        int u1 = __ldg(&eidx[start + j + 1]);
        uint2 q0 = __ldg((const uint2*)(y + (size_t)u0 * H) + lane);
        uint2 q1 = __ldg((const uint2*)(y + (size_t)u1 * H) + lane);
        float2 a0 = __half22float2(*(__half2*)&q0.x);
        float2 a1 = __half22float2(*(__half2*)&q0.y);
        float2 b0 = __half22float2(*(__half2*)&q1.x);
        float2 b1 = __half22float2(*(__half2*)&q1.y);
        acc.x += a0.x + b0.x; acc.y += a0.y + b0.y;
        acc.z += a1.x + b1.x; acc.w += a1.y + b1.y;
    }
    if (j < deg) {
        int u = __ldg(&eidx[start + j]);
        uint2 q = __ldg((const uint2*)(y + (size_t)u * H) + lane);
        float2 a0 = __half22float2(*(__half2*)&q.x);
        float2 a1 = __half22float2(*(__half2*)&q.y);
        acc.x += a0.x; acc.y += a0.y; acc.z += a1.x; acc.w += a1.y;
    }
    float s = rsq_deg(deg);
    float4 bb = *(const float4*)(bias + lane * 4);
    float4 o;
    o.x = fmaxf(fmaf(s, acc.x, bb.x), 0.f);
    o.y = fmaxf(fmaf(s, acc.y, bb.y), 0.f);
    o.z = fmaxf(fmaf(s, acc.z, bb.z), 0.f);
    o.w = fmaxf(fmaf(s, acc.w, bb.w), 0.f);
    if (LAST) {
        int g = __ldg(&seg[v]);
        red_add_v4(gsum + (size_t)g * H + lane * 4, o);
    } else {
        float sc = rsq_deg(__ldg(&co[v]));
        __half2 h0 = __floats2half2_rn(o.x * sc, o.y * sc);
        __half2 h1 = __floats2half2_rn(o.z * sc, o.w * sc);
        uint2 w2; w2.x = *(unsigned*)&h0; w2.y = *(unsigned*)&h1;
        *(uint2*)(xo + (size_t)v * H + lane * 4) = w2;
    }
}

// ---------------- readout MLP ----------------------------------------------
__global__ void k_mlp(const float* __restrict__ gsum, const float* __restrict__ esum,
                      const float* __restrict__ gcnt, const float* __restrict__ ecnt,
                      const float* __restrict__ r1w, const float* __restrict__ r1b,
                      const float* __restrict__ r2w, const float* __restrict__ r2b,
                      float* __restrict__ out) {
    __shared__ float x[2 * H];
    __shared__ float red[4];
    int b = blockIdx.x;
    int j = threadIdx.x;
    float ig = 1.f / fmaxf(gcnt[b], 1.f);
    float ie = 1.f / fmaxf(ecnt[b], 1.f);
    x[j]     = gsum[b * H + j] * ig;
    x[H + j] = esum[b * H + j] * ie;
    __syncthreads();
    float acc = __ldg(&r1b[j]);
    #pragma unroll 8
    for (int i = 0; i < 2 * H; i++) acc += x[i] * __ldg(&r1w[i * H + j]);
    float sig = 1.f / (1.f + expf(-acc));
    float val = acc * sig * __ldg(&r2w[j]);
    #pragma unroll
    for (int o = 16; o > 0; o >>= 1) val += __shfl_xor_sync(0xffffffffu, val, o);
    if ((j & 31) == 0) red[j >> 5] = val;
    __syncthreads();
    if (j == 0) out[b] = red[0] + red[1] + red[2] + red[3] + __ldg(&r2b[0]);
}

// ---------------- host -----------------------------------------------------
static inline int zgrid(long long n4) {
    long long b = (n4 + 255) / 256;
    return (int)(b < 8192 ? b : 8192);
}

extern "C" void kernel_launch(void* const* d_in, const int* in_sizes, int n_in,
                              void* d_out, int out_size) {
    const int*   z    = (const int*)d_in[0];
    const float* dd   = (const float*)d_in[1];
    const int*   src  = (const int*)d_in[2];
    const int*   dst  = (const int*)d_in[3];
    const int*   lsrc = (const int*)d_in[4];
    const int*   ldst = (const int*)d_in[5];
    const int*   ng   = (const int*)d_in[6];
    const int*   eg   = (const int*)d_in[7];
    const float* emb  = (const float*)d_in[8];
    const float* epw  = (const float*)d_in[9];
    const float* epb  = (const float*)d_in[10];
    const float* gW   = (const float*)d_in[11];
    const float* gb   = (const float*)d_in[12];
    const float* lgW  = (const float*)d_in[13];
    const float* lgb  = (const float*)d_in[14];
    const float* r1w  = (const float*)d_in[15];
    const float* r1b  = (const float*)d_in[16];
    const float* r2w  = (const float*)d_in[17];
    const float* r2b  = (const float*)d_in[18];

    int N  = in_sizes[0];
    int E  = in_sizes[2];
    int E2 = in_sizes[4];
    int B  = out_size;
    float* out = (float*)d_out;

    __half *hx, *ex, *yh, *ye;
    float *red;
    int *cntG, *cntL, *offG, *offL, *curG, *curL, *eidxG, *eidxL, *bsum;
    cudaGetSymbolAddress((void**)&hx, d_hx);
    cudaGetSymbolAddress((void**)&ex, d_ex);
    cudaGetSymbolAddress((void**)&yh, d_yh);
    cudaGetSymbolAddress((void**)&ye, d_ye);
    cudaGetSymbolAddress((void**)&cntG, d_cntG);
    cudaGetSymbolAddress((void**)&cntL, d_cntL);
    cudaGetSymbolAddress((void**)&offG, d_offG);
    cudaGetSymbolAddress((void**)&offL, d_offL);
    cudaGetSymbolAddress((void**)&curG, d_curG);
    cudaGetSymbolAddress((void**)&curL, d_curL);
    cudaGetSymbolAddress((void**)&eidxG, d_eidxG);
    cudaGetSymbolAddress((void**)&eidxL, d_eidxL);
    cudaGetSymbolAddress((void**)&bsum, d_bsum);
    cudaGetSymbolAddress((void**)&red, d_red);

    float* gsum = red;
    float* esum = red + (size_t)B * H;
    float* gcnt = red + (size_t)2 * B * H;
    float* ecnt = gcnt + B;

    cudaFuncSetAttribute(k_gemm, cudaFuncAttributeMaxDynamicSharedMemorySize, GEMM_SMEM);

    // ---- line-graph front matter (k_gemm is the 4th launch: ncu target) ----
    k_zero_f4<<<zgrid((long long)2 * E / 4), 256>>>((float4*)cntL, (long long)2 * E / 4); // 1
    k_count<<<2048, 256>>>(lsrc, ldst, cntL, cntL + E, E2);                                // 2
    k_init_e<<<((long long)E * 32 + 255) / 256, 256>>>(dd, epw, epb, cntL, ex, E);         // 3
    k_gemm<<<GEMM_BLOCKS, 256, GEMM_SMEM>>>(ex, lgW, ye, E);                               // 4 <- profiled
    {
        long long nred4 = ((long long)2 * B * H + 2 * B) / 4;
        k_zero_f4<<<zgrid(nred4), 256>>>((float4*)red, nred4);
    }

    // ---- node-graph front matter ----
    k_zero_f4<<<zgrid((long long)2 * N / 4), 256>>>((float4*)cntG, (long long)2 * N / 4);
    k_count<<<2048, 256>>>(src, dst, cntG, cntG + N, E);
    k_init_h<<<((long long)N * 32 + 255) / 256, 256>>>(z, emb, cntG, hx, N);

    // ---- CSR by destination (line graph) ----
    int nbL = (E + SCAN_ELEMS - 1) / SCAN_ELEMS;
    k_scan1<<<nbL, 1024>>>(cntL + E, offL, bsum, E);
    k_scan2<<<1, 1024>>>(bsum, nbL);
    k_scan3<<<nbL, 1024>>>(offL, bsum, E);
    k_copy_i<<<2048, 256>>>(offL, curL, E);
    k_fill<<<2048, 256>>>(lsrc, ldst, curL, eidxL, E2);

    // ---- line-graph layers ----
    long long aggE = ((long long)E * 32 + 255) / 256;
    k_agg<0><<<aggE, 256>>>(ye, eidxL, offL, cntL + E, cntL,
                            lgb, ex, eg, esum, E);
    for (int l = 1; l < NLAY; l++) {
        k_gemm<<<GEMM_BLOCKS, 256, GEMM_SMEM>>>(ex, lgW + (size_t)l * H * H, ye, E);
        if (l < NLAY - 1)
            k_agg<0><<<aggE, 256>>>(ye, eidxL, offL, cntL + E, cntL,
                                    lgb + (size_t)l * H, ex, eg, esum, E);
        else
            k_agg<1><<<aggE, 256>>>(ye, eidxL, offL, cntL + E, cntL,
                                    lgb + (size_t)l * H, ex, eg, esum, E);
    }

    // ---- CSR by destination (node graph) ----
    int nbG = (N + SCAN_ELEMS - 1) / SCAN_ELEMS;
    k_scan1<<<nbG, 1024>>>(cntG + N, offG, bsum, N);
    k_scan2<<<1, 1024>>>(bsum, nbG);
    k_scan3<<<nbG, 1024>>>(offG, bsum, N);
    k_copy_i<<<512, 256>>>(offG, curG, N);
    k_fill<<<2048, 256>>>(src, dst, curG, eidxG, E);

    // ---- node-graph layers ----
    long long aggN = ((long long)N * 32 + 255) / 256;
    for (int l = 0; l < NLAY; l++) {
        k_gemm<<<GEMM_BLOCKS, 256, GEMM_SMEM>>>(hx, gW + (size_t)l * H * H, yh, N);
        if (l < NLAY - 1)
            k_agg<0><<<aggN, 256>>>(yh, eidxG, offG, cntG + N, cntG,
                                    gb + (size_t)l * H, hx, ng, gsum, N);
        else
            k_agg<1><<<aggN, 256>>>(yh, eidxG, offG, cntG + N, cntG,
                                    gb + (size_t)l * H, hx, ng, gsum, N);
    }

    // ---- per-graph counts + readout ----
    k_segcnt<<<512, 256>>>(ng, gcnt, N);
    k_segcnt<<<2048, 256>>>(eg, ecnt, E);
    k_mlp<<<B, 128>>>(gsum, esum, gcnt, ecnt, r1w, r1b, r2w, r2b, out);
}